// round 8
// baseline (speedup 1.0000x reference)
#include <cuda_runtime.h>

#define B 256
#define C 50000
#define D 512
#define ALPHA 0.5f

// ---- scan blocks (first in grid = wave 1) ----
#define OH_SLICES 8
#define NB_OH (B * OH_SLICES)       // 2048
#define OH_ROW4 (C / 4)             // 12500 float4 per row
#define OH_PER_SLICE 1563
#define SCAN_ITERS 7                // 7*256 >= 1563

// ---- copy blocks: 256 thr x 8 float4 = 16 rows of D=512 ----
#define COPY_PER_THREAD 8
#define ROWS_PER_BLOCK 16
#define NB_COPY ((C * D / 4) / (256 * COPY_PER_THREAD))  // 3125, exact
#define NB_TOTAL (NB_OH + NB_COPY)

__device__ int g_labels[B];
__device__ unsigned int g_scan = 0;   // scan-block completion counter
__device__ unsigned int g_fin  = 0;   // copy-block completion counter

__global__ void __launch_bounds__(256) center_loss_kernel(
    const float* __restrict__ x,
    const float* __restrict__ onehot,
    const float* __restrict__ centers,
    float* __restrict__ result,
    float* __restrict__ new_centers) {
    int blk = blockIdx.x;
    int tid = threadIdx.x;

    if (blk < NB_OH) {
        // ========== scan: iota-dot over slice; finder writes label+result ==
        int b = blk >> 3;
        int slice = blk & 7;
        const float4* row = reinterpret_cast<const float4*>(onehot) +
                            (size_t)b * OH_ROW4;
        int lo = slice * OH_PER_SLICE;
        int hi = lo + OH_PER_SLICE;
        if (hi > OH_ROW4) hi = OH_ROW4;

        float acc = 0.0f;
        #pragma unroll
        for (int k = 0; k < SCAN_ITERS; k++) {
            int i = lo + tid + k * 256;
            float4 v = (i < hi) ? row[i] : make_float4(0.f, 0.f, 0.f, 0.f);
            float fi = (float)(4 * i);
            acc += v.x * (fi + 1.0f);
            acc += v.y * (fi + 2.0f);
            acc += v.z * (fi + 3.0f);
            acc += v.w * (fi + 4.0f);
        }

        __shared__ float s_warp[8];
        __shared__ float s_sum;
        #pragma unroll
        for (int off = 16; off > 0; off >>= 1)
            acc += __shfl_down_sync(0xFFFFFFFFu, acc, off);
        if ((tid & 31) == 0) s_warp[tid >> 5] = acc;
        __syncthreads();
        if (tid == 0) {
            float t = 0.0f;
            #pragma unroll
            for (int w = 0; w < 8; w++) t += s_warp[w];
            s_sum = t;
        }
        __syncthreads();

        float s = s_sum;
        if (s > 0.5f) {
            int l = (int)(s + 0.5f) - 1;   // exact: s == label+1
            if (tid == 0) g_labels[b] = l;

            // result[b] = ||x[b] - centers[l]||^2
            const float* xb = x + (size_t)b * D;
            const float* cl = centers + (size_t)l * D;
            float r = 0.0f;
            #pragma unroll
            for (int k = 0; k < D / 256; k++) {
                int d = tid + k * 256;
                float df = xb[d] - cl[d];
                r += df * df;
            }
            #pragma unroll
            for (int off = 16; off > 0; off >>= 1)
                r += __shfl_down_sync(0xFFFFFFFFu, r, off);
            if ((tid & 31) == 0) s_warp[tid >> 5] = r;
            __syncthreads();
            if (tid == 0) {
                float t = 0.0f;
                #pragma unroll
                for (int w = 0; w < 8; w++) t += s_warp[w];
                result[b] = t;
            }
        }
        // signal scan completion (label write ordered before)
        __syncthreads();
        __threadfence();
        if (tid == 0) atomicAdd(&g_scan, 1u);
    } else {
        // ========== copy 16 rows (unchanged fast path), then fix own rows ==
        int cb = blk - NB_OH;
        const float4* src = reinterpret_cast<const float4*>(centers);
        float4* dst = reinterpret_cast<float4*>(new_centers);
        size_t base = (size_t)cb * (256 * COPY_PER_THREAD) + tid;
        #pragma unroll
        for (int k = 0; k < COPY_PER_THREAD; k++) {
            size_t idx = base + (size_t)k * 256;
            dst[idx] = src[idx];
        }

        // guard: scan complete (expected zero-iteration; copy takes >> scan)
        if (tid == 0) {
            while (atomicAdd(&g_scan, 0u) < NB_OH) __nanosleep(64);
        }
        __syncthreads();
        __threadfence();

        // check owned rows [r0, r0+16) against the 256 labels
        __shared__ int s_lab[B];
        __shared__ unsigned int s_mask;
        s_lab[tid] = g_labels[tid];
        if (tid == 0) s_mask = 0u;
        __syncthreads();

        int r0 = cb * ROWS_PER_BLOCK;
        int l = s_lab[tid];
        if (l >= r0 && l < r0 + ROWS_PER_BLOCK)
            atomicOr(&s_mask, 1u << (l - r0));
        __syncthreads();

        if (s_mask != 0u) {
            unsigned int mask = s_mask;
            while (mask) {
                int ri = __ffs(mask) - 1;
                mask &= mask - 1;
                int row = r0 + ri;
                int n = 0;
                float sx0 = 0.0f, sx1 = 0.0f;
                for (int m = 0; m < B; m++) {
                    if (s_lab[m] == row) {
                        n++;
                        const float* xm = x + (size_t)m * D;
                        sx0 += xm[tid];
                        sx1 += xm[tid + 256];
                    }
                }
                float inv = 1.0f / ((float)n + 1.0f);
                float fn = (float)n;
                size_t rb = (size_t)row * D;
                float c0 = centers[rb + tid];
                float c1 = centers[rb + tid + 256];
                new_centers[rb + tid]       = c0 - ALPHA * (fn * c0 - sx0) * inv;
                new_centers[rb + tid + 256] = c1 - ALPHA * (fn * c1 - sx1) * inv;
            }
        }

        // retire; very last copy block resets counters for graph replay
        __syncthreads();
        if (tid == 0) {
            __threadfence();
            unsigned int f = atomicAdd(&g_fin, 1u);
            if (f == NB_COPY - 1) {
                g_scan = 0;
                g_fin = 0;
                __threadfence();
            }
        }
    }
}

extern "C" void kernel_launch(void* const* d_in, const int* in_sizes, int n_in,
                              void* d_out, int out_size) {
    const float* x       = (const float*)d_in[0];
    const float* onehot  = (const float*)d_in[1];
    const float* centers = (const float*)d_in[2];

    float* result      = (float*)d_out;        // [B, 1]
    float* new_centers = (float*)d_out + B;    // [C, D]

    center_loss_kernel<<<NB_TOTAL, 256>>>(x, onehot, centers,
                                          result, new_centers);
}

// round 9
// speedup vs baseline: 1.2247x; 1.2247x over previous
#include <cuda_runtime.h>

#define B 256
#define C 50000
#define D 512
#define ALPHA 0.5f

// ---- scan blocks (first in grid = wave 1) ----
#define OH_SLICES 8
#define NB_OH (B * OH_SLICES)       // 2048
#define OH_ROW4 (C / 4)             // 12500 float4 per row
#define OH_PER_SLICE 1563
#define SCAN_ITERS 7                // 7*256 >= 1563

// ---- copy blocks: 256 thr x 8 float4 = 16 rows of D=512 ----
#define COPY_PER_THREAD 8
#define NB_COPY ((C * D / 4) / (256 * COPY_PER_THREAD))  // 3125, exact

// ---- fixup blocks: LAST in grid, dispatched as copy waves retire ----
#define NB_FIX B                    // 256
#define NB_TOTAL (NB_OH + NB_COPY + NB_FIX)   // 5429

__device__ int g_labels[B];
__device__ unsigned int g_scan = 0;   // scan completion counter
__device__ unsigned int g_fin  = 0;   // fixup completion counter (for reset)

__global__ void __launch_bounds__(256) center_loss_kernel(
    const float* __restrict__ x,
    const float* __restrict__ onehot,
    const float* __restrict__ centers,
    float* __restrict__ result,
    float* __restrict__ new_centers) {
    int blk = blockIdx.x;
    int tid = threadIdx.x;

    if (blk < NB_OH) {
        // ========== scan: iota-dot; finder block writes label + result =====
        int b = blk >> 3;
        int slice = blk & 7;
        const float4* row = reinterpret_cast<const float4*>(onehot) +
                            (size_t)b * OH_ROW4;
        int lo = slice * OH_PER_SLICE;
        int hi = lo + OH_PER_SLICE;
        if (hi > OH_ROW4) hi = OH_ROW4;

        float acc = 0.0f;
        #pragma unroll
        for (int k = 0; k < SCAN_ITERS; k++) {
            int i = lo + tid + k * 256;
            float4 v = (i < hi) ? row[i] : make_float4(0.f, 0.f, 0.f, 0.f);
            float fi = (float)(4 * i);
            acc += v.x * (fi + 1.0f);
            acc += v.y * (fi + 2.0f);
            acc += v.z * (fi + 3.0f);
            acc += v.w * (fi + 4.0f);
        }

        __shared__ float s_warp[8];
        __shared__ float s_sum;
        #pragma unroll
        for (int off = 16; off > 0; off >>= 1)
            acc += __shfl_down_sync(0xFFFFFFFFu, acc, off);
        if ((tid & 31) == 0) s_warp[tid >> 5] = acc;
        __syncthreads();
        if (tid == 0) {
            float t = 0.0f;
            #pragma unroll
            for (int w = 0; w < 8; w++) t += s_warp[w];
            s_sum = t;
        }
        __syncthreads();

        float s = s_sum;
        if (s > 0.5f) {
            int l = (int)(s + 0.5f) - 1;   // exact: s == label+1
            if (tid == 0) g_labels[b] = l;

            // result[b] = ||x[b] - centers[l]||^2
            const float* xb = x + (size_t)b * D;
            const float* cl = centers + (size_t)l * D;
            float r = 0.0f;
            #pragma unroll
            for (int k = 0; k < D / 256; k++) {
                int d = tid + k * 256;
                float df = xb[d] - cl[d];
                r += df * df;
            }
            #pragma unroll
            for (int off = 16; off > 0; off >>= 1)
                r += __shfl_down_sync(0xFFFFFFFFu, r, off);
            if ((tid & 31) == 0) s_warp[tid >> 5] = r;
            __syncthreads();
            if (tid == 0) {
                float t = 0.0f;
                #pragma unroll
                for (int w = 0; w < 8; w++) t += s_warp[w];
                result[b] = t;
            }
        }
        // signal scan completion
        __syncthreads();
        __threadfence();
        if (tid == 0) atomicAdd(&g_scan, 1u);
    } else if (blk < NB_OH + NB_COPY) {
        // ========== pure copy: byte-identical to the proven fast path ======
        int cb = blk - NB_OH;
        const float4* src = reinterpret_cast<const float4*>(centers);
        float4* dst = reinterpret_cast<float4*>(new_centers);
        size_t base = (size_t)cb * (256 * COPY_PER_THREAD) + tid;
        #pragma unroll
        for (int k = 0; k < COPY_PER_THREAD; k++) {
            size_t idx = base + (size_t)k * 256;
            dst[idx] = src[idx];
        }
    } else {
        // ========== fixup: last 256 blocks, dispatched in the final waves ==
        int b = blk - NB_OH - NB_COPY;

        // guard: scan done (scan finished ~20us before these blocks launch;
        // expected zero-iteration spin)
        if (tid == 0) {
            while (atomicAdd(&g_scan, 0u) < NB_OH) __nanosleep(64);
        }
        __syncthreads();
        __threadfence();

        __shared__ int s_lab[B];
        __shared__ int s_match[B];
        __shared__ int s_cnt;
        __shared__ int s_first;

        s_lab[tid] = g_labels[tid];
        if (tid == 0) { s_cnt = 0; s_first = B; }
        __syncthreads();

        int l = s_lab[b];
        if (s_lab[tid] == l) {
            int pos = atomicAdd(&s_cnt, 1);
            s_match[pos] = tid;
            atomicMin(&s_first, tid);
        }
        __syncthreads();

        if (b == s_first) {   // lowest-indexed holder rewrites the row
            int n = s_cnt;
            float inv = 1.0f / ((float)n + 1.0f);
            float fn = (float)n;
            #pragma unroll
            for (int k = 0; k < D / 256; k++) {
                int d = tid + k * 256;
                float sx = 0.0f;
                for (int m = 0; m < n; m++)
                    sx += x[(size_t)s_match[m] * D + d];
                float c = centers[(size_t)l * D + d];
                new_centers[(size_t)l * D + d] =
                    c - ALPHA * (fn * c - sx) * inv;
            }
        }

        // retire; last fixup block resets counters (graph replay determinism)
        __syncthreads();
        if (tid == 0) {
            unsigned int f = atomicAdd(&g_fin, 1u);
            if (f == NB_FIX - 1) {
                g_scan = 0;
                g_fin = 0;
                __threadfence();
            }
        }
    }
}

extern "C" void kernel_launch(void* const* d_in, const int* in_sizes, int n_in,
                              void* d_out, int out_size) {
    const float* x       = (const float*)d_in[0];
    const float* onehot  = (const float*)d_in[1];
    const float* centers = (const float*)d_in[2];

    float* result      = (float*)d_out;        // [B, 1]
    float* new_centers = (float*)d_out + B;    // [C, D]

    center_loss_kernel<<<NB_TOTAL, 256>>>(x, onehot, centers,
                                          result, new_centers);
}